// round 9
// baseline (speedup 1.0000x reference)
#include <cuda_runtime.h>
#include <cuda_fp16.h>
#include <cstdint>

// ---------------- Problem constants ----------------
#define HB   1024          // NUM_BASIC (K)
#define HM   8192          // NUM_MIXED (GEMM M)
#define RR   735           // T*7*7 rows of X (GEMM N, logical)
#define RPAD 768           // padded N
#define NN   57            // output matrix dim
#define OUTN (NN*NN)       // 3249

// ---------------- Scratch (device globals; no allocs allowed) ----------------
__device__ __half g_Xh[RPAD * HB];             // 1.5 MB : X in fp16, rows 735..767 zero
__device__ __half g_Wh[HM * HB];               // 16.7 MB: W in fp16 (RN)
__device__ float  g_Y [(size_t)HM * RPAD];     // 25 MB  : relu(X@W^T + b), [hm][r]

// ---------------- helpers ----------------
__device__ __forceinline__ void cp16(uint32_t s, const void* g) {
    asm volatile("cp.async.cg.shared.global [%0], [%1], 16;" :: "r"(s), "l"(g));
}
__device__ __forceinline__ void mma_f16(float* c, const uint32_t* a, const uint32_t* b) {
    asm volatile(
        "mma.sync.aligned.m16n8k16.row.col.f32.f16.f16.f32 "
        "{%0,%1,%2,%3}, {%4,%5,%6,%7}, {%8,%9}, {%0,%1,%2,%3};"
        : "+f"(c[0]), "+f"(c[1]), "+f"(c[2]), "+f"(c[3])
        : "r"(a[0]), "r"(a[1]), "r"(a[2]), "r"(a[3]), "r"(b[0]), "r"(b[1]));
}
__device__ __forceinline__ void ldsm4(uint32_t* r, uint32_t addr) {
    asm volatile("ldmatrix.sync.aligned.m8n8.x4.shared.b16 {%0,%1,%2,%3}, [%4];"
        : "=r"(r[0]), "=r"(r[1]), "=r"(r[2]), "=r"(r[3]) : "r"(addr));
}

// ---------------- Kernel 1: fused prep (convert W + build X) ----------------
// blocks 0..99     : build_x  (p = b>>1 in 0..49, h-half = b&1)
// blocks 100..1123 : convert_w (512 threads x 4 independent float4 chains)
__global__ __launch_bounds__(512) void prep_kernel(const float* __restrict__ mat,
                                                   const float* __restrict__ te,
                                                   const float4* __restrict__ W) {
    const int b = blockIdx.x;
    if (b < 100) {
        const int p = b >> 1;
        const int h = (b & 1) * 512 + threadIdx.x;
        if (p == 49) {  // zero padding rows 735..767
            #pragma unroll
            for (int row = RR; row < RPAD; row++) g_Xh[row * HB + h] = __ushort_as_half(0);
            return;
        }
        const int m = p / 7, n = p % 7;
        const float mv = fmaxf(mat[h * 49 + n * 7 + m], 0.f);
        const int rb = m * 7 + n;
        #pragma unroll
        for (int t = 0; t < 15; t++) {
            float s = 1.f + 1.f / (1.f + __expf(-te[h * 15 + t]));
            g_Xh[(t * 49 + rb) * HB + h] = __float2half_rn(s * mv);
        }
    } else {
        // 1024 blocks x 2048 float4 each covers HM*HB floats
        const int base = (b - 100) * 2048;
        float4 v[4];
        int idx[4];
        #pragma unroll
        for (int j = 0; j < 4; j++) {
            idx[j] = base + threadIdx.x + j * 512;
            v[j] = W[idx[j]];
        }
        #pragma unroll
        for (int j = 0; j < 4; j++) {
            __half2 h2[2];
            h2[0] = __floats2half2_rn(v[j].x, v[j].y);
            h2[1] = __floats2half2_rn(v[j].z, v[j].w);
            *reinterpret_cast<uint2*>(&g_Wh[(size_t)idx[j] * 4]) =
                *reinterpret_cast<uint2*>(h2);
        }
    }
}

// ---------------- Kernel 2: fp16 mma.sync GEMM, ldmatrix fragments ----------------
// C[M=8192(hm)][N=768(r)] = g_Wh @ g_Xh^T ; epilogue: relu(C + b[hm]) -> g_Y
#define KTH 32             // K halfs per smem stage
#define KSH 40             // smem row stride in halfs: 80B rows -> conflict-free LDSM/STS
#define KTILES (HB / KTH)  // 32
#define NSTAGE 3
#define STAGE_H (128 * KSH)                 // halfs per array per stage
#define GEMM_DYN (NSTAGE * 2 * STAGE_H * 2) // 61440 bytes

extern __shared__ __half g_sm[];

__global__ __launch_bounds__(256, 2) void gemm_kernel(const float* __restrict__ bias) {
    const int tid  = threadIdx.x;
    const int lane = tid & 31, warp = tid >> 5;
    const int g  = lane >> 2, t4 = lane & 3;
    const int mb = (warp >> 1) * 32;   // warp grid 4(M) x 2(N)
    const int nb = (warp & 1) * 64;
    const int m0 = blockIdx.y * 128;
    const int n0 = blockIdx.x * 128;

    const int lrow = tid >> 1;            // 0..127
    const int lkc  = (tid & 1) * 2;       // 16B chunk pair

    const uint32_t sBase = (uint32_t)__cvta_generic_to_shared(g_sm);

    const __half* Ag = g_Wh + (size_t)(m0 + lrow) * HB;
    const __half* Bg = g_Xh + (size_t)(n0 + lrow) * HB;

    // ldmatrix per-lane address offsets (bytes, relative to stage base)
    const int q  = lane >> 3, rr = lane & 7;
    uint32_t aOff[2], bOff[4];
    {
        const int aRow = (q & 1) * 8 + rr, aK = (q >> 1) * 8;
        const int bN   = (q >> 1) * 8 + rr, bK = (q & 1) * 8;
        #pragma unroll
        for (int mt = 0; mt < 2; mt++)
            aOff[mt] = (uint32_t)(((mb + mt * 16 + aRow) * KSH + aK) * 2);
        #pragma unroll
        for (int p = 0; p < 4; p++)
            bOff[p] = (uint32_t)((STAGE_H + (nb + p * 16 + bN) * KSH + bK) * 2);
    }

    float c[2][8][4];
    #pragma unroll
    for (int i = 0; i < 2; i++)
        #pragma unroll
        for (int j = 0; j < 8; j++)
            #pragma unroll
            for (int qq = 0; qq < 4; qq++) c[i][j][qq] = 0.f;

    auto load_stage = [&](int s, int kt) {
        const int k0 = kt * KTH;
        uint32_t sa = sBase + (uint32_t)(s * (2 * STAGE_H)) * 2u;
        uint32_t sb = sa + (uint32_t)STAGE_H * 2u;
        #pragma unroll
        for (int cch = 0; cch < 2; cch++) {
            int kh = (lkc + cch) * 8;
            cp16(sa + (uint32_t)(lrow * KSH + kh) * 2u, Ag + k0 + kh);
            cp16(sb + (uint32_t)(lrow * KSH + kh) * 2u, Bg + k0 + kh);
        }
        asm volatile("cp.async.commit_group;");
    };

    load_stage(0, 0);
    load_stage(1, 1);

    #pragma unroll 1
    for (int kt = 0; kt < KTILES; kt++) {
        if (kt < KTILES - 2) asm volatile("cp.async.wait_group 1;");
        else                 asm volatile("cp.async.wait_group 0;");
        __syncthreads();
        int cur = kt % NSTAGE;
        if (kt + 2 < KTILES) load_stage((kt + 2) % NSTAGE, kt + 2);

        const uint32_t stBase = sBase + (uint32_t)(cur * (2 * STAGE_H)) * 2u;
        #pragma unroll
        for (int s16 = 0; s16 < 2; s16++) {
            const uint32_t khB = (uint32_t)(s16 * 16 * 2);
            uint32_t a[2][4], b[4][4];
            ldsm4(a[0], stBase + aOff[0] + khB);
            ldsm4(a[1], stBase + aOff[1] + khB);
            #pragma unroll
            for (int p = 0; p < 4; p++)
                ldsm4(b[p], stBase + bOff[p] + khB);
            #pragma unroll
            for (int mt = 0; mt < 2; mt++)
                #pragma unroll
                for (int nt = 0; nt < 8; nt++)
                    mma_f16(c[mt][nt], a[mt], &b[nt >> 1][(nt & 1) * 2]);
        }
    }

    // epilogue: +bias, relu, store Y[hm][r]
    #pragma unroll
    for (int mt = 0; mt < 2; mt++) {
        #pragma unroll
        for (int qq = 0; qq < 2; qq++) {
            int row = m0 + mb + mt * 16 + g + qq * 8;
            float bv = bias[row];
            #pragma unroll
            for (int nt = 0; nt < 8; nt++) {
                int col = n0 + nb + nt * 8 + t4 * 2;
                float2 v;
                v.x = fmaxf(c[mt][nt][qq * 2 + 0] + bv, 0.f);
                v.y = fmaxf(c[mt][nt][qq * 2 + 1] + bv, 0.f);
                *reinterpret_cast<float2*>(&g_Y[(size_t)row * RPAD + col]) = v;
            }
        }
    }
}

// ---------------- Kernel 3: assemble + degree-normalize (smem-staged output) ----------------
// mixed[hm,1+row,1+col] = Y[hm, (49-7*(row/7)+col)*7 + row%7]
// row 0 / col 0: identity entries at multiples of 7. d = clip(rowsum,1)^-0.5.
// Scatter into 13KB smem tile, then copy to global with aligned STG.128.
__global__ __launch_bounds__(228) void assemble_kernel(float* __restrict__ out) {
    __shared__ float sy[RR + 1];
    __shared__ float sd[NN];
    __shared__ float psum[4][NN + 1];
    __shared__ int   rbase[NN];
    __shared__ float so[OUTN];          // staged 57x57 output tile

    const int tid = threadIdx.x;
    const int jc  = tid % 57;
    const int ty  = tid / 57;
    const int hm  = blockIdx.x;
    const float* yrow = g_Y + (size_t)hm * RPAD;

    for (int r = tid; r < RR; r += 228) sy[r] = yrow[r];
    if (tid > 0 && tid < NN) {
        int row = tid - 1, j = row / 7, n = row % 7;
        rbase[tid] = (49 - 7 * j) * 7 + n;
    }
    __syncthreads();

    {
        float acc = 0.f;
        if (jc > 0) {
            int base = rbase[jc] + ty * 14 * 7;
            #pragma unroll
            for (int cc = 0; cc < 14; cc++) acc += sy[base + cc * 7];
        }
        psum[ty][jc] = acc;
    }
    __syncthreads();

    if (tid < NN) {
        float s;
        if (tid == 0) s = 9.f;
        else {
            s = psum[0][tid] + psum[1][tid] + psum[2][tid] + psum[3][tid];
            if ((tid % 7) == 0) s += 1.f;
        }
        sd[tid] = (s <= 1.f) ? 1.f : rsqrtf(s);
    }
    __syncthreads();

    const float sdj  = sd[jc];
    const bool  jc7  = (jc % 7) == 0;
    const int   gcol = (jc - 1) * 7;

    #pragma unroll
    for (int it = 0; it < 15; it++) {
        int i = ty + it * 4;
        if (i >= NN) break;
        float v;
        if (i == 0)        v = jc7 ? sd[0] * sdj : 0.f;
        else if (jc == 0)  v = ((i % 7) == 0) ? sd[i] * sd[0] : 0.f;
        else               v = sd[i] * sdj * sy[rbase[i] + gcol];
        so[i * NN + jc] = v;
    }
    __syncthreads();

    // linear copy so -> out+ob with STG.128 after alignment head
    float* dst = out + (size_t)hm * OUTN;
    const int head = (4 - (int)(((uintptr_t)dst >> 2) & 3)) & 3;
    if (tid < head) dst[tid] = so[tid];
    const int nv = (OUTN - head) >> 2;            // float4 count
    for (int v4 = tid; v4 < nv; v4 += 228) {
        int e = head + v4 * 4;
        float4 t;
        t.x = so[e]; t.y = so[e + 1]; t.z = so[e + 2]; t.w = so[e + 3];
        *reinterpret_cast<float4*>(dst + e) = t;
    }
    const int tail = head + nv * 4;
    if (tid < OUTN - tail) dst[tail + tid] = so[tail + tid];
}

// ---------------- launch ----------------
extern "C" void kernel_launch(void* const* d_in, const int* in_sizes, int n_in,
                              void* d_out, int out_size) {
    const float* mat = (const float*)d_in[0];
    const float* te  = (const float*)d_in[1];
    const float* W   = (const float*)d_in[2];
    const float* b   = (const float*)d_in[3];
    float* out = (float*)d_out;

    cudaFuncSetAttribute(gemm_kernel, cudaFuncAttributeMaxDynamicSharedMemorySize, GEMM_DYN);

    prep_kernel<<<1124, 512>>>(mat, te, (const float4*)W);
    gemm_kernel<<<dim3(6, 64), 256, GEMM_DYN>>>(b);
    assemble_kernel<<<HM, 228>>>(out);
}